// round 5
// baseline (speedup 1.0000x reference)
#include <cuda_runtime.h>
#include <cstdint>

#define N_TOK 4096
#define TD    384
#define KNB   64
#define PD    128
#define HD    256
#define LN_EPS 1e-5f

// ---------------- device scratch (no allocs allowed) ----------------
__device__ __align__(16) float g_proj[N_TOK * 256];   // [n][0:128]=xp1, [128:256]=xp2
__device__ __align__(16) float g_Wxt[256 * TD];       // Wxt[p][t]
__device__ __align__(16) float g_W1t[256 * 128];      // W1t[j][p]
__device__ __align__(16) float g_W2t[128 * 256];      // W2t[i][j]

// bool inputs are materialized by the harness as 4-byte words (int32 or
// float32 — only those dtypes exist in metadata). Nonzero bit pattern = true
// for both encodings.
__device__ __forceinline__ bool bval(const unsigned int* b, int i) {
    return b[i] != 0u;
}

// ---------------- kernel 1: weight transposes ----------------
__global__ void transpose_k(const float* __restrict__ Wx,
                            const float* __restrict__ W1,
                            const float* __restrict__ W2) {
    int stride = gridDim.x * blockDim.x;
    int tid = blockIdx.x * blockDim.x + threadIdx.x;
    for (int i = tid; i < TD * 256; i += stride) {
        int t = i >> 8, p = i & 255;
        g_Wxt[p * TD + t] = Wx[i];
    }
    for (int i = tid; i < 128 * 256; i += stride) {
        int p = i >> 8, j = i & 255;
        g_W1t[j * 128 + p] = W1[i];
    }
    for (int i = tid; i < 256 * 128; i += stride) {
        int j = i >> 7, p = i & 127;
        g_W2t[p * 256 + j] = W2[i];
    }
}

// ---------------- kernel 2: proj = LN(x * mask) @ Wx ----------------
// 8 token-rows per block, 256 threads. LN per row by one warp, then
// register-blocked GEMV: thread = output column p (256 cols), 8 accumulators.
__global__ __launch_bounds__(256) void proj_k(const float* __restrict__ x,
                                              const unsigned int* __restrict__ mask,
                                              const float* __restrict__ ln_g,
                                              const float* __restrict__ ln_b) {
    __shared__ float xs[8 * TD];   // 12 KB
    int n0 = blockIdx.x * 8;
    int tid = threadIdx.x;

    // load x rows, apply token mask
    for (int i = tid; i < 8 * TD; i += 256) {
        int r = i / TD;
        float mf = bval(mask, n0 + r) ? 1.0f : 0.0f;
        xs[i] = x[n0 * TD + i] * mf;
    }
    __syncthreads();

    // LayerNorm: warp w normalizes row w (384 elems, 12/lane)
    {
        int warp = tid >> 5, lane = tid & 31;
        int r = warp;
        float v[12];
        float s = 0.0f;
#pragma unroll
        for (int q = 0; q < 12; q++) { v[q] = xs[r * TD + lane + q * 32]; s += v[q]; }
#pragma unroll
        for (int o = 16; o; o >>= 1) s += __shfl_xor_sync(0xffffffffu, s, o);
        float mu = s * (1.0f / (float)TD);
        float vs = 0.0f;
#pragma unroll
        for (int q = 0; q < 12; q++) { float d = v[q] - mu; vs += d * d; }
#pragma unroll
        for (int o = 16; o; o >>= 1) vs += __shfl_xor_sync(0xffffffffu, vs, o);
        float rstd = rsqrtf(vs * (1.0f / (float)TD) + LN_EPS);
#pragma unroll
        for (int q = 0; q < 12; q++) {
            int t = lane + q * 32;
            xs[r * TD + t] = (v[q] - mu) * rstd * ln_g[t] + ln_b[t];
        }
    }
    __syncthreads();

    // GEMM: acc[r] += LN(x)[r][t] * Wx[t][p], vectorized over t via Wxt
    float acc[8];
#pragma unroll
    for (int r = 0; r < 8; r++) acc[r] = 0.0f;
    const float4* wx  = (const float4*)(g_Wxt + tid * TD);
    const float4* xs4 = (const float4*)xs;
    for (int t4 = 0; t4 < TD / 4; t4++) {
        float4 w = wx[t4];
#pragma unroll
        for (int r = 0; r < 8; r++) {
            float4 xv = xs4[r * (TD / 4) + t4];
            acc[r] = fmaf(w.x, xv.x, acc[r]);
            acc[r] = fmaf(w.y, xv.y, acc[r]);
            acc[r] = fmaf(w.z, xv.z, acc[r]);
            acc[r] = fmaf(w.w, xv.w, acc[r]);
        }
    }
#pragma unroll
    for (int r = 0; r < 8; r++) g_proj[(n0 + r) * 256 + tid] = acc[r];
}

// ---------------- kernel 3: fused pair update + transition ----------------
// One block = one token n, one half of K (32 rows). 256 threads.
// smem: z(4096) zln(4096) h(8192) xp2(128) pm(32) idx(32) tg(128) tb(128)
//       = 16832 floats = 67,328 bytes (dynamic)
__global__ __launch_bounds__(256) void main_k(const float* __restrict__ pair_rep,
                                              const unsigned int* __restrict__ mask,
                                              const int* __restrict__ nbr,
                                              const unsigned int* __restrict__ slot,
                                              const float* __restrict__ t_g,
                                              const float* __restrict__ t_b,
                                              const float* __restrict__ b1,
                                              const float* __restrict__ b2,
                                              float* __restrict__ out) {
    extern __shared__ float sm[];
    float* z_s   = sm;            // 32*128
    float* zln_s = sm + 4096;     // 32*128
    float* h_s   = sm + 8192;     // 32*256
    float* xp2_s = sm + 16384;    // 128
    float* pm_s  = sm + 16512;    // 32
    int*   idx_s = (int*)(sm + 16544); // 32
    float* tg_s  = sm + 16576;    // 128
    float* tb_s  = sm + 16704;    // 128

    int tid   = threadIdx.x;
    int n     = blockIdx.y;
    int kbase = blockIdx.x * 32;

    if (tid < 128) {
        xp2_s[tid] = g_proj[n * 256 + 128 + tid];
        tg_s[tid]  = t_g[tid];
        tb_s[tid]  = t_b[tid];
    } else if (tid < 160) {
        int r = tid - 128;
        int k = kbase + r;
        int idx = nbr[n * KNB + k];
        idx_s[r] = idx;
        bool pm = bval(mask, n) && bval(mask, idx) && bval(slot, n * KNB + k);
        pm_s[r] = pm ? 1.0f : 0.0f;
    }
    __syncthreads();

    // z = (pair_rep + xp2 + xp1[nbr]) * pm
    {
        int p  = tid & 127;
        int r0 = tid >> 7;  // 0 or 1
#pragma unroll
        for (int rr = 0; rr < 32; rr += 2) {
            int r = rr + r0;
            int row = n * KNB + kbase + r;
            float z = (pair_rep[row * PD + p] + xp2_s[p] +
                       g_proj[idx_s[r] * 256 + p]) * pm_s[r];
            z_s[r * PD + p] = z;
        }
    }
    __syncthreads();

    // LayerNorm(z) per row: warp w handles rows 4w..4w+3
    {
        int warp = tid >> 5, lane = tid & 31;
#pragma unroll
        for (int rr = 0; rr < 4; rr++) {
            int r = (warp << 2) + rr;
            float v0 = z_s[r * PD + lane];
            float v1 = z_s[r * PD + lane + 32];
            float v2 = z_s[r * PD + lane + 64];
            float v3 = z_s[r * PD + lane + 96];
            float s = v0 + v1 + v2 + v3;
#pragma unroll
            for (int o = 16; o; o >>= 1) s += __shfl_xor_sync(0xffffffffu, s, o);
            float mu = s * (1.0f / 128.0f);
            float d0 = v0 - mu, d1 = v1 - mu, d2 = v2 - mu, d3 = v3 - mu;
            float vs = d0 * d0 + d1 * d1 + d2 * d2 + d3 * d3;
#pragma unroll
            for (int o = 16; o; o >>= 1) vs += __shfl_xor_sync(0xffffffffu, vs, o);
            float rstd = rsqrtf(vs * (1.0f / 128.0f) + LN_EPS);
            zln_s[r * PD + lane]      = d0 * rstd * tg_s[lane]      + tb_s[lane];
            zln_s[r * PD + lane + 32] = d1 * rstd * tg_s[lane + 32] + tb_s[lane + 32];
            zln_s[r * PD + lane + 64] = d2 * rstd * tg_s[lane + 64] + tb_s[lane + 64];
            zln_s[r * PD + lane + 96] = d3 * rstd * tg_s[lane + 96] + tb_s[lane + 96];
        }
    }
    __syncthreads();

    // phase 1: h[r][j] = relu(zln[r] . W1[:,j] + b1[j]); thread = col j, 32 rows
    {
        int j = tid;
        float acc[32];
#pragma unroll
        for (int r = 0; r < 32; r++) acc[r] = 0.0f;
        const float4* w1  = (const float4*)(g_W1t + j * 128);
        const float4* zl4 = (const float4*)zln_s;
        for (int p4 = 0; p4 < 32; p4++) {
            float4 w = w1[p4];
#pragma unroll
            for (int r = 0; r < 32; r++) {
                float4 zz = zl4[r * 32 + p4];   // warp-broadcast
                acc[r] = fmaf(w.x, zz.x, acc[r]);
                acc[r] = fmaf(w.y, zz.y, acc[r]);
                acc[r] = fmaf(w.z, zz.z, acc[r]);
                acc[r] = fmaf(w.w, zz.w, acc[r]);
            }
        }
        float bb = b1[j];
#pragma unroll
        for (int r = 0; r < 32; r++) h_s[r * HD + j] = fmaxf(acc[r] + bb, 0.0f);
    }
    __syncthreads();

    // phase 2: out[r][i] = (z + h[r] . W2[:,i] + b2[i]) * pm
    {
        int i = tid & 127;
        int g = tid >> 7;  // row group: 0 -> rows 0..15, 1 -> rows 16..31
        float acc[16];
#pragma unroll
        for (int r = 0; r < 16; r++) acc[r] = 0.0f;
        const float4* w2 = (const float4*)(g_W2t + i * 256);
        const float4* h4 = (const float4*)h_s;
        for (int j4 = 0; j4 < 64; j4++) {
            float4 w = w2[j4];
#pragma unroll
            for (int rr = 0; rr < 16; rr++) {
                int r = g * 16 + rr;
                float4 hh = h4[r * 64 + j4];    // warp-broadcast
                acc[rr] = fmaf(w.x, hh.x, acc[rr]);
                acc[rr] = fmaf(w.y, hh.y, acc[rr]);
                acc[rr] = fmaf(w.z, hh.z, acc[rr]);
                acc[rr] = fmaf(w.w, hh.w, acc[rr]);
            }
        }
        float bb = b2[i];
#pragma unroll
        for (int rr = 0; rr < 16; rr++) {
            int r = g * 16 + rr;
            float pm = pm_s[r];
            // pm is binary: (z + t)*pm == z*pm + t*pm, and z already carries pm
            float res = (z_s[r * PD + i] + acc[rr] + bb) * pm;
            out[(n * KNB + kbase + r) * PD + i] = res;
        }
    }
}

// ---------------- launcher ----------------
extern "C" void kernel_launch(void* const* d_in, const int* in_sizes, int n_in,
                              void* d_out, int out_size) {
    const float*        x        = (const float*)d_in[0];
    const float*        pair_rep = (const float*)d_in[1];
    const unsigned int* mask     = (const unsigned int*)d_in[2];  // bool -> 4-byte word
    const int*          nbr      = (const int*)d_in[3];
    const unsigned int* slot     = (const unsigned int*)d_in[4];  // bool -> 4-byte word
    const float*        ln_g     = (const float*)d_in[5];
    const float*        ln_b     = (const float*)d_in[6];
    const float*        Wx       = (const float*)d_in[7];
    const float*        t_g      = (const float*)d_in[8];
    const float*        t_b      = (const float*)d_in[9];
    const float*        W1       = (const float*)d_in[10];
    const float*        b1       = (const float*)d_in[11];
    const float*        W2       = (const float*)d_in[12];
    const float*        b2       = (const float*)d_in[13];
    float*              out      = (float*)d_out;

    transpose_k<<<64, 256>>>(Wx, W1, W2);
    proj_k<<<N_TOK / 8, 256>>>(x, mask, ln_g, ln_b);

    const size_t smem_bytes = 16832 * sizeof(float);  // 67,328 B
    cudaFuncSetAttribute(main_k, cudaFuncAttributeMaxDynamicSharedMemorySize,
                         (int)smem_bytes);
    dim3 grid(2, N_TOK);
    main_k<<<grid, 256, smem_bytes>>>(pair_rep, mask, nbr, slot,
                                      t_g, t_b, b1, b2, out);
}

// round 6
// speedup vs baseline: 4.1765x; 4.1765x over previous
#include <cuda_runtime.h>
#include <cuda_bf16.h>
#include <cstdint>

#define N_TOK 4096
#define TD    384
#define KNB   64
#define PD    128
#define HD    256
#define LN_EPS 1e-5f

// ---------------- device scratch (no allocs allowed) ----------------
__device__ __align__(16) float g_proj[N_TOK * 256];   // [n][0:128]=xp1, [128:256]=xp2
__device__ __align__(16) float g_Wxt[256 * TD];       // Wxt[p][t] for proj GEMV
// Weight fragments for mma.sync.m16n8k16 (bf16), pre-packed in B-fragment order.
// W1f: K=128 (8 k-tiles) x N=256 (32 n-tiles) ; W2f: K=256 (16) x N=128 (16)
__device__ __align__(16) uint2 g_W1f[8 * 32 * 32];
__device__ __align__(16) uint2 g_W2f[16 * 16 * 32];

// bool inputs arrive as 4-byte words (int32/float32); nonzero = true.
__device__ __forceinline__ bool bval(const unsigned int* b, int i) { return b[i] != 0u; }

__device__ __forceinline__ uint32_t pack2bf(float a, float b) {
    __nv_bfloat162 t = __floats2bfloat162_rn(a, b);   // x=a (low), y=b (high)
    return *reinterpret_cast<uint32_t*>(&t);
}

__device__ __forceinline__ uint32_t smem_u32(const void* p) {
    uint32_t a;
    asm("{ .reg .u64 t; cvta.to.shared.u64 t, %1; cvt.u32.u64 %0, t; }" : "=r"(a) : "l"(p));
    return a;
}

__device__ __forceinline__ void ldsm_x4(uint32_t* a, uint32_t addr) {
    asm volatile("ldmatrix.sync.aligned.m8n8.x4.shared.b16 {%0,%1,%2,%3}, [%4];"
                 : "=r"(a[0]), "=r"(a[1]), "=r"(a[2]), "=r"(a[3]) : "r"(addr));
}

__device__ __forceinline__ void mma16816(float* c, const uint32_t* a, uint2 b) {
    asm volatile(
        "mma.sync.aligned.m16n8k16.row.col.f32.bf16.bf16.f32 "
        "{%0,%1,%2,%3}, {%4,%5,%6,%7}, {%8,%9}, {%0,%1,%2,%3};"
        : "+f"(c[0]), "+f"(c[1]), "+f"(c[2]), "+f"(c[3])
        : "r"(a[0]), "r"(a[1]), "r"(a[2]), "r"(a[3]), "r"(b.x), "r"(b.y));
}

// ---------------- kernel 1: weight prep (transpose Wx, pack W1/W2 frags) ----
__global__ void prep_k(const float* __restrict__ Wx,
                       const float* __restrict__ W1,
                       const float* __restrict__ W2) {
    int stride = gridDim.x * blockDim.x;
    int tid = blockIdx.x * blockDim.x + threadIdx.x;
    for (int i = tid; i < TD * 256; i += stride) {
        int t = i >> 8, p = i & 255;
        g_Wxt[p * TD + t] = Wx[i];
    }
    // W1 frags: b0 = (k0, k0+1) col j ; b1 = (k0+8, k0+9) col j
    for (int e = tid; e < 8 * 32 * 32; e += stride) {
        int lane = e & 31, jt = (e >> 5) & 31, kt = e >> 10;
        int tig = lane & 3, g = lane >> 2;
        int j = jt * 8 + g;
        int k0 = kt * 16 + tig * 2;
        g_W1f[e] = make_uint2(
            pack2bf(W1[k0 * HD + j], W1[(k0 + 1) * HD + j]),
            pack2bf(W1[(k0 + 8) * HD + j], W1[(k0 + 9) * HD + j]));
    }
    for (int e = tid; e < 16 * 16 * 32; e += stride) {
        int lane = e & 31, it = (e >> 5) & 15, kt = e >> 9;
        int tig = lane & 3, g = lane >> 2;
        int i = it * 8 + g;
        int k0 = kt * 16 + tig * 2;
        g_W2f[e] = make_uint2(
            pack2bf(W2[k0 * PD + i], W2[(k0 + 1) * PD + i]),
            pack2bf(W2[(k0 + 8) * PD + i], W2[(k0 + 9) * PD + i]));
    }
}

// ---------------- kernel 2: proj = LN(x * mask) @ Wx (unchanged, passing) ----
__global__ __launch_bounds__(256) void proj_k(const float* __restrict__ x,
                                              const unsigned int* __restrict__ mask,
                                              const float* __restrict__ ln_g,
                                              const float* __restrict__ ln_b) {
    __shared__ float xs[8 * TD];
    int n0 = blockIdx.x * 8;
    int tid = threadIdx.x;

    for (int i = tid; i < 8 * TD; i += 256) {
        int r = i / TD;
        float mf = bval(mask, n0 + r) ? 1.0f : 0.0f;
        xs[i] = x[n0 * TD + i] * mf;
    }
    __syncthreads();
    {
        int warp = tid >> 5, lane = tid & 31;
        int r = warp;
        float v[12];
        float s = 0.0f;
#pragma unroll
        for (int q = 0; q < 12; q++) { v[q] = xs[r * TD + lane + q * 32]; s += v[q]; }
#pragma unroll
        for (int o = 16; o; o >>= 1) s += __shfl_xor_sync(0xffffffffu, s, o);
        float mu = s * (1.0f / (float)TD);
        float vs = 0.0f;
#pragma unroll
        for (int q = 0; q < 12; q++) { float d = v[q] - mu; vs += d * d; }
#pragma unroll
        for (int o = 16; o; o >>= 1) vs += __shfl_xor_sync(0xffffffffu, vs, o);
        float rstd = rsqrtf(vs * (1.0f / (float)TD) + LN_EPS);
#pragma unroll
        for (int q = 0; q < 12; q++) {
            int t = lane + q * 32;
            xs[r * TD + t] = (v[q] - mu) * rstd * ln_g[t] + ln_b[t];
        }
    }
    __syncthreads();

    float acc[8];
#pragma unroll
    for (int r = 0; r < 8; r++) acc[r] = 0.0f;
    const float4* wx  = (const float4*)(g_Wxt + tid * TD);
    const float4* xs4 = (const float4*)xs;
    for (int t4 = 0; t4 < TD / 4; t4++) {
        float4 w = wx[t4];
#pragma unroll
        for (int r = 0; r < 8; r++) {
            float4 xv = xs4[r * (TD / 4) + t4];
            acc[r] = fmaf(w.x, xv.x, acc[r]);
            acc[r] = fmaf(w.y, xv.y, acc[r]);
            acc[r] = fmaf(w.z, xv.z, acc[r]);
            acc[r] = fmaf(w.w, xv.w, acc[r]);
        }
    }
#pragma unroll
    for (int r = 0; r < 8; r++) g_proj[(n0 + r) * 256 + tid] = acc[r];
}

// ---------------- kernel 3: fused pair update + transition (tensor cores) ----
// One CTA = one token n = 64 rows. 256 threads = 8 warps.
// smem (bytes):
//   z_s   fp32 [64][132]   @0       33792   (padded: +4 floats/row)
//   zln   bf16 [64][136]   @33792   17408   (272B row stride -> 4-bank advance)
//   h     bf16 [64][264]   @51200   33792   (528B row stride)
//   xp2   fp32 [128]       @84992   512
//   pm    fp32 [64]        @85504   256
//   idx   int  [64]        @85760   256     -> total 86016
#define SM_Z    0
#define SM_ZLN  33792
#define SM_H    51200
#define SM_XP2  84992
#define SM_PM   85504
#define SM_IDX  85760
#define SM_TOT  86016
#define ZSTR    132     // fp32 elems per z row
#define LSTR    136     // bf16 elems per zln row
#define HSTR    264     // bf16 elems per h row

__global__ __launch_bounds__(256) void main_k(const float* __restrict__ pair_rep,
                                              const unsigned int* __restrict__ mask,
                                              const int* __restrict__ nbr,
                                              const unsigned int* __restrict__ slot,
                                              const float* __restrict__ t_g,
                                              const float* __restrict__ t_b,
                                              const float* __restrict__ b1,
                                              const float* __restrict__ b2,
                                              float* __restrict__ out) {
    extern __shared__ char smb[];
    float* z_s   = (float*)(smb + SM_Z);
    char*  zln_b = smb + SM_ZLN;
    char*  h_b   = smb + SM_H;
    float* xp2_s = (float*)(smb + SM_XP2);
    float* pm_s  = (float*)(smb + SM_PM);
    int*   idx_s = (int*)(smb + SM_IDX);

    int tid  = threadIdx.x;
    int warp = tid >> 5, lane = tid & 31;
    int g    = lane >> 2, tig = lane & 3;
    int n    = blockIdx.x;

    if (tid < 128) {
        xp2_s[tid] = g_proj[n * 256 + 128 + tid];
    } else if (tid < 192) {
        int r = tid - 128;
        int idx = nbr[n * KNB + r];
        idx_s[r] = idx;
        bool pm = bval(mask, n) && bval(mask, idx) && bval(slot, n * KNB + r);
        pm_s[r] = pm ? 1.0f : 0.0f;
    }
    __syncthreads();

    // ---- z = (pair_rep + xp2 + xp1[nbr]) * pm ----
    {
        int pc = (tid & 31) * 4;
        int rb = tid >> 5;
#pragma unroll
        for (int it = 0; it < 8; it++) {
            int r = it * 8 + rb;
            const float4 pr = *(const float4*)&pair_rep[((size_t)(n * KNB + r)) * PD + pc];
            const float4 xj = *(const float4*)&g_proj[idx_s[r] * 256 + pc];
            const float4 xo = *(const float4*)&xp2_s[pc];
            float pm = pm_s[r];
            float4 z;
            z.x = (pr.x + xo.x + xj.x) * pm;
            z.y = (pr.y + xo.y + xj.y) * pm;
            z.z = (pr.z + xo.z + xj.z) * pm;
            z.w = (pr.w + xo.w + xj.w) * pm;
            *(float4*)&z_s[r * ZSTR + pc] = z;
        }
    }
    __syncthreads();

    // ---- LayerNorm(z) -> zln (bf16, padded) ; warp handles 8 rows ----
    {
        float4 tg4 = *(const float4*)&t_g[4 * lane];
        float4 tb4 = *(const float4*)&t_b[4 * lane];
#pragma unroll
        for (int rr = 0; rr < 8; rr++) {
            int r = warp * 8 + rr;
            float4 v = *(const float4*)&z_s[r * ZSTR + 4 * lane];
            float s = v.x + v.y + v.z + v.w;
#pragma unroll
            for (int o = 16; o; o >>= 1) s += __shfl_xor_sync(0xffffffffu, s, o);
            float mu = s * (1.0f / 128.0f);
            float d0 = v.x - mu, d1 = v.y - mu, d2 = v.z - mu, d3 = v.w - mu;
            float vs = d0 * d0 + d1 * d1 + d2 * d2 + d3 * d3;
#pragma unroll
            for (int o = 16; o; o >>= 1) vs += __shfl_xor_sync(0xffffffffu, vs, o);
            float rstd = rsqrtf(vs * (1.0f / 128.0f) + LN_EPS);
            uint2 pk;
            pk.x = pack2bf(d0 * rstd * tg4.x + tb4.x, d1 * rstd * tg4.y + tb4.y);
            pk.y = pack2bf(d2 * rstd * tg4.z + tb4.z, d3 * rstd * tg4.w + tb4.w);
            *(uint2*)(zln_b + r * (LSTR * 2) + 8 * lane) = pk;
        }
    }
    __syncthreads();

    // ---- phase 1: h = relu(zln @ W1 + b1) ; warp covers 32 N-cols ----
    {
        uint32_t zln_u = smem_u32(zln_b);
        float c1[4][4][4];
#pragma unroll
        for (int mt = 0; mt < 4; mt++)
#pragma unroll
            for (int nt = 0; nt < 4; nt++)
#pragma unroll
                for (int q = 0; q < 4; q++) c1[mt][nt][q] = 0.0f;

#pragma unroll
        for (int kt = 0; kt < 8; kt++) {
            uint32_t a[4][4];
#pragma unroll
            for (int mt = 0; mt < 4; mt++) {
                uint32_t addr = zln_u +
                    ((mt * 16 + (lane & 15)) * LSTR + kt * 16 + (lane >> 4) * 8) * 2;
                ldsm_x4(a[mt], addr);
            }
            uint2 bf[4];
#pragma unroll
            for (int nt = 0; nt < 4; nt++)
                bf[nt] = g_W1f[((kt * 32) + (warp * 4 + nt)) * 32 + lane];
#pragma unroll
            for (int mt = 0; mt < 4; mt++)
#pragma unroll
                for (int nt = 0; nt < 4; nt++)
                    mma16816(c1[mt][nt], a[mt], bf[nt]);
        }
        // epilogue: +b1, relu, bf16 -> h smem
#pragma unroll
        for (int nt = 0; nt < 4; nt++) {
            int j0 = warp * 32 + nt * 8 + tig * 2;
            float2 bb = *(const float2*)&b1[j0];
#pragma unroll
            for (int mt = 0; mt < 4; mt++) {
                int r0 = mt * 16 + g;
                float* c = c1[mt][nt];
                *(uint32_t*)(h_b + r0 * (HSTR * 2) + j0 * 2) =
                    pack2bf(fmaxf(c[0] + bb.x, 0.0f), fmaxf(c[1] + bb.y, 0.0f));
                *(uint32_t*)(h_b + (r0 + 8) * (HSTR * 2) + j0 * 2) =
                    pack2bf(fmaxf(c[2] + bb.x, 0.0f), fmaxf(c[3] + bb.y, 0.0f));
            }
        }
    }
    __syncthreads();

    // ---- phase 2: out = (z + h @ W2 + b2) * pm ; warp covers 16 N-cols ----
    {
        uint32_t h_u = smem_u32(h_b);
        float c2[4][2][4];
#pragma unroll
        for (int mt = 0; mt < 4; mt++)
#pragma unroll
            for (int nt = 0; nt < 2; nt++)
#pragma unroll
                for (int q = 0; q < 4; q++) c2[mt][nt][q] = 0.0f;

#pragma unroll
        for (int kt = 0; kt < 16; kt++) {
            uint32_t a[4][4];
#pragma unroll
            for (int mt = 0; mt < 4; mt++) {
                uint32_t addr = h_u +
                    ((mt * 16 + (lane & 15)) * HSTR + kt * 16 + (lane >> 4) * 8) * 2;
                ldsm_x4(a[mt], addr);
            }
            uint2 bf[2];
#pragma unroll
            for (int nt = 0; nt < 2; nt++)
                bf[nt] = g_W2f[((kt * 16) + (warp * 2 + nt)) * 32 + lane];
#pragma unroll
            for (int mt = 0; mt < 4; mt++)
#pragma unroll
                for (int nt = 0; nt < 2; nt++)
                    mma16816(c2[mt][nt], a[mt], bf[nt]);
        }
        // epilogue: + b2 + z residual, * pm, write out
#pragma unroll
        for (int nt = 0; nt < 2; nt++) {
            int i0 = warp * 16 + nt * 8 + tig * 2;
            float2 bb = *(const float2*)&b2[i0];
#pragma unroll
            for (int mt = 0; mt < 4; mt++) {
                float* c = c2[mt][nt];
                int r0 = mt * 16 + g;
                {
                    float pm = pm_s[r0];
                    float2 zz = *(const float2*)&z_s[r0 * ZSTR + i0];
                    float2 o;
                    o.x = (zz.x + c[0] + bb.x) * pm;
                    o.y = (zz.y + c[1] + bb.y) * pm;
                    *(float2*)&out[((size_t)(n * KNB + r0)) * PD + i0] = o;
                }
                {
                    int r1 = r0 + 8;
                    float pm = pm_s[r1];
                    float2 zz = *(const float2*)&z_s[r1 * ZSTR + i0];
                    float2 o;
                    o.x = (zz.x + c[2] + bb.x) * pm;
                    o.y = (zz.y + c[3] + bb.y) * pm;
                    *(float2*)&out[((size_t)(n * KNB + r1)) * PD + i0] = o;
                }
            }
        }
    }
}

// ---------------- launcher ----------------
extern "C" void kernel_launch(void* const* d_in, const int* in_sizes, int n_in,
                              void* d_out, int out_size) {
    const float*        x        = (const float*)d_in[0];
    const float*        pair_rep = (const float*)d_in[1];
    const unsigned int* mask     = (const unsigned int*)d_in[2];
    const int*          nbr      = (const int*)d_in[3];
    const unsigned int* slot     = (const unsigned int*)d_in[4];
    const float*        ln_g     = (const float*)d_in[5];
    const float*        ln_b     = (const float*)d_in[6];
    const float*        Wx       = (const float*)d_in[7];
    const float*        t_g      = (const float*)d_in[8];
    const float*        t_b      = (const float*)d_in[9];
    const float*        W1       = (const float*)d_in[10];
    const float*        b1       = (const float*)d_in[11];
    const float*        W2       = (const float*)d_in[12];
    const float*        b2       = (const float*)d_in[13];
    float*              out      = (float*)d_out;

    prep_k<<<96, 256>>>(Wx, W1, W2);
    proj_k<<<N_TOK / 8, 256>>>(x, mask, ln_g, ln_b);

    cudaFuncSetAttribute(main_k, cudaFuncAttributeMaxDynamicSharedMemorySize, SM_TOT);
    main_k<<<N_TOK, 256, SM_TOT>>>(pair_rep, mask, nbr, slot,
                                   t_g, t_b, b1, b2, out);
}

// round 7
// speedup vs baseline: 7.4260x; 1.7781x over previous
#include <cuda_runtime.h>
#include <cuda_bf16.h>
#include <cstdint>

#define N_TOK 4096
#define TD    384
#define KNB   64
#define PD    128
#define HD    256
#define LN_EPS 1e-5f

// ---------------- device scratch (no allocs allowed) ----------------
__device__ __align__(16) float g_proj[N_TOK * 256];   // [n][0:128]=xp1, [128:256]=xp2
// Weight fragments for mma.sync.m16n8k16 (bf16), pre-packed in B-fragment order.
__device__ __align__(16) uint2 g_W1f[8 * 32 * 32];    // K=128 (8 kt) x N=256 (32 nt)
__device__ __align__(16) uint2 g_W2f[16 * 16 * 32];   // K=256 (16 kt) x N=128 (16 nt)

// bool inputs arrive as 4-byte words (int32/float32); nonzero = true.
__device__ __forceinline__ bool bval(const unsigned int* b, int i) { return b[i] != 0u; }

__device__ __forceinline__ uint32_t pack2bf(float a, float b) {
    __nv_bfloat162 t = __floats2bfloat162_rn(a, b);
    return *reinterpret_cast<uint32_t*>(&t);
}

__device__ __forceinline__ uint32_t smem_u32(const void* p) {
    uint32_t a;
    asm("{ .reg .u64 t; cvta.to.shared.u64 t, %1; cvt.u32.u64 %0, t; }" : "=r"(a) : "l"(p));
    return a;
}

__device__ __forceinline__ void ldsm_x4(uint32_t* a, uint32_t addr) {
    asm volatile("ldmatrix.sync.aligned.m8n8.x4.shared.b16 {%0,%1,%2,%3}, [%4];"
                 : "=r"(a[0]), "=r"(a[1]), "=r"(a[2]), "=r"(a[3]) : "r"(addr));
}

__device__ __forceinline__ void mma16816(float* c, const uint32_t* a, uint2 b) {
    asm volatile(
        "mma.sync.aligned.m16n8k16.row.col.f32.bf16.bf16.f32 "
        "{%0,%1,%2,%3}, {%4,%5,%6,%7}, {%8,%9}, {%0,%1,%2,%3};"
        : "+f"(c[0]), "+f"(c[1]), "+f"(c[2]), "+f"(c[3])
        : "r"(a[0]), "r"(a[1]), "r"(a[2]), "r"(a[3]), "r"(b.x), "r"(b.y));
}

// ---------------- kernel 1: fused proj + weight packing --------------------
// blocks [0, 512): proj = LN(x*mask) @ Wx (8 token-rows each, Wx read direct)
// blocks [512, 544): pack W1/W2 into mma B-fragment order
#define PROJ_BLOCKS 512
#define PACK_BLOCKS 32

__global__ __launch_bounds__(256) void fused_k(const float* __restrict__ x,
                                               const unsigned int* __restrict__ mask,
                                               const float* __restrict__ ln_g,
                                               const float* __restrict__ ln_b,
                                               const float* __restrict__ Wx,
                                               const float* __restrict__ W1,
                                               const float* __restrict__ W2) {
    __shared__ float xs[8 * TD];
    int tid = threadIdx.x;

    if (blockIdx.x >= PROJ_BLOCKS) {
        // ---- weight fragment packing ----
        int t0 = (blockIdx.x - PROJ_BLOCKS) * 256 + tid;
        int stride = PACK_BLOCKS * 256;
        for (int e = t0; e < 8 * 32 * 32; e += stride) {
            int lane = e & 31, jt = (e >> 5) & 31, kt = e >> 10;
            int tig = lane & 3, g = lane >> 2;
            int j = jt * 8 + g;
            int k0 = kt * 16 + tig * 2;
            g_W1f[e] = make_uint2(
                pack2bf(W1[k0 * HD + j], W1[(k0 + 1) * HD + j]),
                pack2bf(W1[(k0 + 8) * HD + j], W1[(k0 + 9) * HD + j]));
        }
        for (int e = t0; e < 16 * 16 * 32; e += stride) {
            int lane = e & 31, it = (e >> 5) & 15, kt = e >> 9;
            int tig = lane & 3, g = lane >> 2;
            int i = it * 8 + g;
            int k0 = kt * 16 + tig * 2;
            g_W2f[e] = make_uint2(
                pack2bf(W2[k0 * PD + i], W2[(k0 + 1) * PD + i]),
                pack2bf(W2[(k0 + 8) * PD + i], W2[(k0 + 9) * PD + i]));
        }
        return;
    }

    // ---- proj ----
    int n0 = blockIdx.x * 8;
    for (int i = tid; i < 8 * TD; i += 256) {
        int r = i / TD;
        float mf = bval(mask, n0 + r) ? 1.0f : 0.0f;
        xs[i] = x[n0 * TD + i] * mf;
    }
    __syncthreads();
    {
        int warp = tid >> 5, lane = tid & 31;
        int r = warp;
        float v[12];
        float s = 0.0f, s2 = 0.0f;
#pragma unroll
        for (int q = 0; q < 12; q++) {
            v[q] = xs[r * TD + lane + q * 32];
            s += v[q]; s2 += v[q] * v[q];
        }
#pragma unroll
        for (int o = 16; o; o >>= 1) {
            s  += __shfl_xor_sync(0xffffffffu, s, o);
            s2 += __shfl_xor_sync(0xffffffffu, s2, o);
        }
        float mu = s * (1.0f / (float)TD);
        float var = s2 * (1.0f / (float)TD) - mu * mu;
        float rstd = rsqrtf(var + LN_EPS);
#pragma unroll
        for (int q = 0; q < 12; q++) {
            int t = lane + q * 32;
            xs[r * TD + t] = (v[q] - mu) * rstd * ln_g[t] + ln_b[t];
        }
    }
    __syncthreads();

    float acc[8];
#pragma unroll
    for (int r = 0; r < 8; r++) acc[r] = 0.0f;
    const float4* xs4 = (const float4*)xs;
    for (int t4 = 0; t4 < TD / 4; t4++) {
        // Wx[t][p]: warp-coalesced 128B per t
        float w0 = Wx[(t4 * 4 + 0) * 256 + tid];
        float w1 = Wx[(t4 * 4 + 1) * 256 + tid];
        float w2 = Wx[(t4 * 4 + 2) * 256 + tid];
        float w3 = Wx[(t4 * 4 + 3) * 256 + tid];
#pragma unroll
        for (int r = 0; r < 8; r++) {
            float4 xv = xs4[r * (TD / 4) + t4];
            acc[r] = fmaf(w0, xv.x, acc[r]);
            acc[r] = fmaf(w1, xv.y, acc[r]);
            acc[r] = fmaf(w2, xv.z, acc[r]);
            acc[r] = fmaf(w3, xv.w, acc[r]);
        }
    }
#pragma unroll
    for (int r = 0; r < 8; r++) g_proj[(n0 + r) * 256 + tid] = acc[r];
}

// ---------------- kernel 2: fused pair update + transition (tensor cores) ---
// One CTA = 32 pair-rows (half a token). 256 threads = 8 warps. grid = 8192.
// smem (bytes):
//   z_s  fp32 [32][132] @0      16896
//   zln  bf16 [32][136] @16896   8704   (272B row stride -> 4-bank advance)
//   h    bf16 [32][264] @25600  16896   (528B row stride)
//   xp2  fp32 [128]     @42496    512
//   pm   fp32 [32]      @43008    128
//   idx  int  [32]      @43136    128   -> total 43264
#define SM_Z    0
#define SM_ZLN  16896
#define SM_H    25600
#define SM_XP2  42496
#define SM_PM   43008
#define SM_IDX  43136
#define SM_TOT  43264
#define ZSTR    132
#define LSTR    136
#define HSTR    264

__global__ __launch_bounds__(256, 4) void main_k(const float* __restrict__ pair_rep,
                                                 const unsigned int* __restrict__ mask,
                                                 const int* __restrict__ nbr,
                                                 const unsigned int* __restrict__ slot,
                                                 const float* __restrict__ t_g,
                                                 const float* __restrict__ t_b,
                                                 const float* __restrict__ b1,
                                                 const float* __restrict__ b2,
                                                 float* __restrict__ out) {
    extern __shared__ char smb[];
    float* z_s   = (float*)(smb + SM_Z);
    char*  zln_b = smb + SM_ZLN;
    char*  h_b   = smb + SM_H;
    float* xp2_s = (float*)(smb + SM_XP2);
    float* pm_s  = (float*)(smb + SM_PM);
    int*   idx_s = (int*)(smb + SM_IDX);

    int tid  = threadIdx.x;
    int warp = tid >> 5, lane = tid & 31;
    int g    = lane >> 2, tig = lane & 3;
    int n     = blockIdx.x >> 1;
    int kbase = (blockIdx.x & 1) * 32;

    if (tid < 128) {
        xp2_s[tid] = g_proj[n * 256 + 128 + tid];
    } else if (tid < 160) {
        int r = tid - 128;
        int k = kbase + r;
        int idx = nbr[n * KNB + k];
        idx_s[r] = idx;
        bool pm = bval(mask, n) && bval(mask, idx) && bval(slot, n * KNB + k);
        pm_s[r] = pm ? 1.0f : 0.0f;
    }
    __syncthreads();

    // ---- z = (pair_rep + xp2 + xp1[nbr]) * pm ----
    {
        int pc = lane * 4;
        int rb = warp;
#pragma unroll
        for (int it = 0; it < 4; it++) {
            int r = it * 8 + rb;
            const float4 pr = *(const float4*)&pair_rep[((size_t)(n * KNB + kbase + r)) * PD + pc];
            const float4 xj = *(const float4*)&g_proj[idx_s[r] * 256 + pc];
            const float4 xo = *(const float4*)&xp2_s[pc];
            float pm = pm_s[r];
            float4 z;
            z.x = (pr.x + xo.x + xj.x) * pm;
            z.y = (pr.y + xo.y + xj.y) * pm;
            z.z = (pr.z + xo.z + xj.z) * pm;
            z.w = (pr.w + xo.w + xj.w) * pm;
            *(float4*)&z_s[r * ZSTR + pc] = z;
        }
    }
    __syncthreads();

    // ---- LayerNorm(z) -> zln (bf16), single-pass sum/sumsq ----
    {
        float4 tg4 = *(const float4*)&t_g[4 * lane];
        float4 tb4 = *(const float4*)&t_b[4 * lane];
#pragma unroll
        for (int rr = 0; rr < 4; rr++) {
            int r = warp * 4 + rr;
            float4 v = *(const float4*)&z_s[r * ZSTR + 4 * lane];
            float s  = v.x + v.y + v.z + v.w;
            float s2 = v.x * v.x + v.y * v.y + v.z * v.z + v.w * v.w;
#pragma unroll
            for (int o = 16; o; o >>= 1) {
                s  += __shfl_xor_sync(0xffffffffu, s, o);
                s2 += __shfl_xor_sync(0xffffffffu, s2, o);
            }
            float mu  = s * (1.0f / 128.0f);
            float var = s2 * (1.0f / 128.0f) - mu * mu;
            float rstd = rsqrtf(var + LN_EPS);
            uint2 pk;
            pk.x = pack2bf((v.x - mu) * rstd * tg4.x + tb4.x,
                           (v.y - mu) * rstd * tg4.y + tb4.y);
            pk.y = pack2bf((v.z - mu) * rstd * tg4.z + tb4.z,
                           (v.w - mu) * rstd * tg4.w + tb4.w);
            *(uint2*)(zln_b + r * (LSTR * 2) + 8 * lane) = pk;
        }
    }
    __syncthreads();

    // ---- phase 1: h = relu(zln @ W1 + b1) ; warp covers 32 N-cols, M=32 ----
    {
        uint32_t zln_u = smem_u32(zln_b);
        float c1[2][4][4];
#pragma unroll
        for (int mt = 0; mt < 2; mt++)
#pragma unroll
            for (int nt = 0; nt < 4; nt++)
#pragma unroll
                for (int q = 0; q < 4; q++) c1[mt][nt][q] = 0.0f;

#pragma unroll
        for (int kt = 0; kt < 8; kt++) {
            uint32_t a[2][4];
#pragma unroll
            for (int mt = 0; mt < 2; mt++) {
                uint32_t addr = zln_u +
                    ((mt * 16 + (lane & 15)) * LSTR + kt * 16 + (lane >> 4) * 8) * 2;
                ldsm_x4(a[mt], addr);
            }
#pragma unroll
            for (int nt = 0; nt < 4; nt++) {
                uint2 bf = g_W1f[((kt * 32) + (warp * 4 + nt)) * 32 + lane];
                mma16816(c1[0][nt], a[0], bf);
                mma16816(c1[1][nt], a[1], bf);
            }
        }
#pragma unroll
        for (int nt = 0; nt < 4; nt++) {
            int j0 = warp * 32 + nt * 8 + tig * 2;
            float2 bb = *(const float2*)&b1[j0];
#pragma unroll
            for (int mt = 0; mt < 2; mt++) {
                int r0 = mt * 16 + g;
                float* c = c1[mt][nt];
                *(uint32_t*)(h_b + r0 * (HSTR * 2) + j0 * 2) =
                    pack2bf(fmaxf(c[0] + bb.x, 0.0f), fmaxf(c[1] + bb.y, 0.0f));
                *(uint32_t*)(h_b + (r0 + 8) * (HSTR * 2) + j0 * 2) =
                    pack2bf(fmaxf(c[2] + bb.x, 0.0f), fmaxf(c[3] + bb.y, 0.0f));
            }
        }
    }
    __syncthreads();

    // ---- phase 2: out = (z + h @ W2 + b2) * pm ; warp covers 16 N-cols ----
    {
        uint32_t h_u = smem_u32(h_b);
        float c2[2][2][4];
#pragma unroll
        for (int mt = 0; mt < 2; mt++)
#pragma unroll
            for (int nt = 0; nt < 2; nt++)
#pragma unroll
                for (int q = 0; q < 4; q++) c2[mt][nt][q] = 0.0f;

#pragma unroll
        for (int kt = 0; kt < 16; kt++) {
            uint32_t a[2][4];
#pragma unroll
            for (int mt = 0; mt < 2; mt++) {
                uint32_t addr = h_u +
                    ((mt * 16 + (lane & 15)) * HSTR + kt * 16 + (lane >> 4) * 8) * 2;
                ldsm_x4(a[mt], addr);
            }
#pragma unroll
            for (int nt = 0; nt < 2; nt++) {
                uint2 bf = g_W2f[((kt * 16) + (warp * 2 + nt)) * 32 + lane];
                mma16816(c2[0][nt], a[0], bf);
                mma16816(c2[1][nt], a[1], bf);
            }
        }
#pragma unroll
        for (int nt = 0; nt < 2; nt++) {
            int i0 = warp * 16 + nt * 8 + tig * 2;
            float2 bb = *(const float2*)&b2[i0];
#pragma unroll
            for (int mt = 0; mt < 2; mt++) {
                float* c = c2[mt][nt];
                int r0 = mt * 16 + g;
                {
                    float pm = pm_s[r0];
                    float2 zz = *(const float2*)&z_s[r0 * ZSTR + i0];
                    float2 o;
                    o.x = (zz.x + c[0] + bb.x) * pm;
                    o.y = (zz.y + c[1] + bb.y) * pm;
                    *(float2*)&out[((size_t)(n * KNB + kbase + r0)) * PD + i0] = o;
                }
                {
                    int r1 = r0 + 8;
                    float pm = pm_s[r1];
                    float2 zz = *(const float2*)&z_s[r1 * ZSTR + i0];
                    float2 o;
                    o.x = (zz.x + c[2] + bb.x) * pm;
                    o.y = (zz.y + c[3] + bb.y) * pm;
                    *(float2*)&out[((size_t)(n * KNB + kbase + r1)) * PD + i0] = o;
                }
            }
        }
    }
}

// ---------------- launcher ----------------
extern "C" void kernel_launch(void* const* d_in, const int* in_sizes, int n_in,
                              void* d_out, int out_size) {
    const float*        x        = (const float*)d_in[0];
    const float*        pair_rep = (const float*)d_in[1];
    const unsigned int* mask     = (const unsigned int*)d_in[2];
    const int*          nbr      = (const int*)d_in[3];
    const unsigned int* slot     = (const unsigned int*)d_in[4];
    const float*        ln_g     = (const float*)d_in[5];
    const float*        ln_b     = (const float*)d_in[6];
    const float*        Wx       = (const float*)d_in[7];
    const float*        t_g      = (const float*)d_in[8];
    const float*        t_b      = (const float*)d_in[9];
    const float*        W1       = (const float*)d_in[10];
    const float*        b1       = (const float*)d_in[11];
    const float*        W2       = (const float*)d_in[12];
    const float*        b2       = (const float*)d_in[13];
    float*              out      = (float*)d_out;

    fused_k<<<PROJ_BLOCKS + PACK_BLOCKS, 256>>>(x, mask, ln_g, ln_b, Wx, W1, W2);

    cudaFuncSetAttribute(main_k, cudaFuncAttributeMaxDynamicSharedMemorySize, SM_TOT);
    main_k<<<2 * N_TOK, 256, SM_TOT>>>(pair_rep, mask, nbr, slot,
                                       t_g, t_b, b1, b2, out);
}